// round 9
// baseline (speedup 1.0000x reference)
#include <cuda_runtime.h>
#include <math.h>

#define NL    2048
#define MODES 4096
#define APL   8

#define LIN1_BLOCKS 512          // 8 warps/block, warp-per-row -> 4096 rows
#define LIN2_BLOCKS 2048         // 8 warps/block, warp-per-row -> 16384 rows
#define X3_BLOCKS   32

// Scratch + sync state (allocation-free __device__ globals)
__device__ float g_x3[NL];
__device__ float g_h[MODES];
__device__ int   g_done_x3;      // counts stage1 blocks done (target 32)
__device__ int   g_done_h;       // counts lin1 blocks done (target 512)
__device__ int   g_fin;          // lin2 completion counter for state reset

// Stable real part of complex tanh(x * (Sr + i*Si)) for real x, fast-fp32.
// Re tanh(a+ib) = sign(a)*(1 - e^{-4|a|}) / (1 + e^{-4|a|} + 2 cos(2b) e^{-2|a|})
__device__ __forceinline__ float re_tanh_cmul_f(float x, float Sr, float Si) {
    float a = x * Sr;
    float b = x * Si;
    float aa = fabsf(a);
    float e2 = __expf(-2.0f * aa);     // arg <= 0
    float e4 = e2 * e2;
    float num = 1.0f - e4;
    if (a < 0.0f) num = -num;
    float den = 1.0f + e4 + 2.0f * __cosf(2.0f * b) * e2;
    return __fdividef(num, den);
}

__device__ __forceinline__ float dot4(float4 w, float4 x) {
    return w.x * x.x + w.y * x.y + w.z * x.z + w.w * x.w;
}

__device__ __forceinline__ void spin_until(const int* ctr, int target) {
    volatile const int* p = ctr;
    while (*p < target) { __nanosleep(64); }
    __threadfence();   // acquire: order subsequent loads after the flag read
}

// Megakernel: stage1 -> lin1 -> lin2 ordered by device-scope counters.
// Dependency chain only ever waits on LOWER block ids, which are scheduled
// first (wave-1 deterministic ascending), so no deadlock is possible.
__global__ void __launch_bounds__(256) mega_kernel(
        const float* __restrict__ model_p,
        const float* __restrict__ w0,
        const float* __restrict__ w1,
        const float* __restrict__ w2,
        const float* __restrict__ lin1_w,
        const float* __restrict__ lin1_b,
        const float* __restrict__ lin2_w,
        const float* __restrict__ lin2_b,
        float* __restrict__ out) {
    const int t    = threadIdx.x;   // 0..255
    const int lane = t & 31;
    const int warp = t >> 5;        // 0..7
    const int bid  = blockIdx.x;

    if (bid < LIN1_BLOCKS) {
        // ================= stage1 (blocks 0..31 only) =================
        if (bid < X3_BLOCKS) {
            __shared__ float Ssh[6];
            __shared__ float red[6][8];

            const int f = bid * 64 + (t & 63);
            float x = __ldg(&model_p[(size_t)f * MODES]);  // column 0 only

            const float4* v0 = reinterpret_cast<const float4*>(w0);
            const float4* v1 = reinterpret_cast<const float4*>(w1);
            const float4* v2 = reinterpret_cast<const float4*>(w2);

            float s0r = 0.f, s0i = 0.f, s1r = 0.f, s1i = 0.f, s2r = 0.f, s2i = 0.f;
            #pragma unroll
            for (int i = t; i < MODES / 2; i += 256) {
                float4 c0 = __ldg(&v0[i]);
                float4 c1 = __ldg(&v1[i]);
                float4 c2 = __ldg(&v2[i]);
                s0r += c0.x + c0.z;  s0i += c0.y + c0.w;
                s1r += c1.x + c1.z;  s1i += c1.y + c1.w;
                s2r += c2.x + c2.z;  s2i += c2.y + c2.w;
            }
            float acc6[6] = {s0r, s0i, s1r, s1i, s2r, s2i};
            #pragma unroll
            for (int k = 0; k < 6; k++) {
                float s = acc6[k];
                #pragma unroll
                for (int o = 16; o > 0; o >>= 1)
                    s += __shfl_xor_sync(0xffffffffu, s, o);
                if (lane == 0) red[k][warp] = s;
            }
            __syncthreads();
            if (t < 6) {
                float s = 0.f;
                #pragma unroll
                for (int w = 0; w < 8; w++) s += red[t][w];
                Ssh[t] = s;
            }
            __syncthreads();

            const float S0r = Ssh[0], S0i = Ssh[1];
            const float S1r = Ssh[2], S1i = Ssh[3];
            const float S2r = Ssh[4], S2i = Ssh[5];

            x = re_tanh_cmul_f(x, S0r, S0i);
            x = re_tanh_cmul_f(x, S1r, S1i);
            x = re_tanh_cmul_f(x, S2r, S2i);
            if (t < 64) g_x3[f] = x;
            __syncthreads();
            if (t == 0) { __threadfence(); atomicAdd(&g_done_x3, 1); }
        }

        // ================= lin1: warp per row =================
        const int r = bid * 8 + warp;
        const float4* __restrict__ row = reinterpret_cast<const float4*>(lin1_w + (size_t)r * NL);

        // Preload first tile's weights (independent of x3), then wait.
        float4 pw0 = row[lane];
        float4 pw1 = row[lane + 32];
        float4 pw2 = row[lane + 64];
        float4 pw3 = row[lane + 96];

        spin_until(&g_done_x3, X3_BLOCKS);

        const float4* __restrict__ x4 = reinterpret_cast<const float4*>(g_x3);
        float a0 = dot4(pw0, __ldg(&x4[lane]));
        float a1 = dot4(pw1, __ldg(&x4[lane + 32]));
        float a2 = dot4(pw2, __ldg(&x4[lane + 64]));
        float a3 = dot4(pw3, __ldg(&x4[lane + 96]));
        #pragma unroll
        for (int base = 128; base < NL / 4; base += 128) {
            int i0 = base + lane;
            a0 += dot4(row[i0],      __ldg(&x4[i0]));
            a1 += dot4(row[i0 + 32], __ldg(&x4[i0 + 32]));
            a2 += dot4(row[i0 + 64], __ldg(&x4[i0 + 64]));
            a3 += dot4(row[i0 + 96], __ldg(&x4[i0 + 96]));
        }
        float acc = (a0 + a1) + (a2 + a3);
        #pragma unroll
        for (int o = 16; o > 0; o >>= 1)
            acc += __shfl_xor_sync(0xffffffffu, acc, o);
        if (lane == 0)
            g_h[r] = tanhf(acc + lin1_b[r]);

        __syncthreads();
        if (t == 0) { __threadfence(); atomicAdd(&g_done_h, 1); }
    } else {
        // ================= lin2: warp per row, 8 load streams =================
        const int r = (bid - LIN1_BLOCKS) * 8 + warp;
        const float4* __restrict__ row = reinterpret_cast<const float4*>(lin2_w + (size_t)r * MODES);

        // Preload first tile's weights (8 chunks) while h is being produced.
        float4 pw[8];
        #pragma unroll
        for (int c = 0; c < 8; c++) pw[c] = row[lane + c * 32];

        spin_until(&g_done_h, LIN1_BLOCKS);

        const float4* __restrict__ v4 = reinterpret_cast<const float4*>(g_h);
        float acc8[8];
        #pragma unroll
        for (int c = 0; c < 8; c++)
            acc8[c] = dot4(pw[c], __ldg(&v4[lane + c * 32]));

        #pragma unroll
        for (int base = 256; base < MODES / 4; base += 256) {
            #pragma unroll
            for (int c = 0; c < 8; c++) {
                int i = base + lane + c * 32;
                acc8[c] += dot4(row[i], __ldg(&v4[i]));
            }
        }
        float acc = ((acc8[0] + acc8[1]) + (acc8[2] + acc8[3])) +
                    ((acc8[4] + acc8[5]) + (acc8[6] + acc8[7]));
        #pragma unroll
        for (int o = 16; o > 0; o >>= 1)
            acc += __shfl_xor_sync(0xffffffffu, acc, o);
        if (lane == 0)
            out[r] = acc + lin2_b[r];

        __syncthreads();
        if (t == 0) {
            int v = atomicAdd(&g_fin, 1);
            if (v == LIN2_BLOCKS - 1) {         // last block resets state for replay
                g_done_x3 = 0;
                g_done_h  = 0;
                g_fin     = 0;
                __threadfence();
            }
        }
    }
}

extern "C" void kernel_launch(void* const* d_in, const int* in_sizes, int n_in,
                              void* d_out, int out_size) {
    // metadata order: model_p, w_fft_0, w_fft_1, w_fft_2, lin1_w, lin1_b, lin2_w, lin2_b
    const float* model_p = (const float*)d_in[0];
    const float* w0      = (const float*)d_in[1];   // complex64 interleaved
    const float* w1      = (const float*)d_in[2];
    const float* w2      = (const float*)d_in[3];
    const float* lin1_w  = (const float*)d_in[4];   // (4096, 2048)
    const float* lin1_b  = (const float*)d_in[5];   // (4096,)
    const float* lin2_w  = (const float*)d_in[6];   // (16384, 4096)
    const float* lin2_b  = (const float*)d_in[7];   // (16384,)
    float* out = (float*)d_out;                     // 16384

    (void)in_sizes; (void)n_in; (void)out_size;

    mega_kernel<<<LIN1_BLOCKS + LIN2_BLOCKS, 256>>>(
        model_p, w0, w1, w2, lin1_w, lin1_b, lin2_w, lin2_b, out);
}